// round 1
// baseline (speedup 1.0000x reference)
#include <cuda_runtime.h>

#define BB   4
#define CC   512
#define NSEQ 4096
#define DQK  64
#define LOG2E 1.4426950408889634f

// ---------------- scratch (static device globals: allocation-free) ----------
__device__ float g_q[BB * DQK * NSEQ];            // [b][d][i]  4 MB
__device__ float g_k[BB * DQK * NSEQ];            // [b][d][j]  4 MB
__device__ float g_v[(size_t)BB * CC * NSEQ];     // [b][c][j] 32 MB
__device__ float g_msc[BB * NSEQ];                // rowmax * LOG2E
__device__ float g_linv[BB * NSEQ];               // 1 / rowsum

// ---------------- fast exp: exp(x) given y = x*LOG2E, y <= ~0 ---------------
// magic-number round-to-nearest + degree-5 Taylor for 2^f on [-0.5,0.5],
// exponent applied via integer add on the float bits. ~9 fixed-lat ops, no MUFU.
__device__ __forceinline__ float exp2_fast(float y) {
    y = fmaxf(y, -120.0f);
    float t = y + 12582912.0f;          // 1.5 * 2^23
    float n = t - 12582912.0f;          // round(y)
    float f = y - n;                    // f in [-0.5, 0.5]
    float p = 1.3333558e-3f;
    p = fmaf(p, f, 9.6181291e-3f);
    p = fmaf(p, f, 5.5504109e-2f);
    p = fmaf(p, f, 2.4022651e-1f);
    p = fmaf(p, f, 6.9314718e-1f);
    p = fmaf(p, f, 1.0f);
    int ni = (int)n;
    return __int_as_float(__float_as_int(p) + (ni << 23));
}

// ---------------- pass 1: QKV projection -----------------------------------
// out[o,n] = sum_c w[o,c] * x[b,c,n];  o in [0,640): 64 q | 64 k | 512 v rows
__global__ __launch_bounds__(256) void proj_kernel(
    const float* __restrict__ x,
    const float* __restrict__ wq, const float* __restrict__ bq,
    const float* __restrict__ wk, const float* __restrict__ bk,
    const float* __restrict__ wv, const float* __restrict__ bv)
{
    __shared__ float ws[16][68];   // [c][o] transposed, padded
    __shared__ float xs[16][64];   // [c][n]

    const int b  = blockIdx.z;
    const int o0 = blockIdx.y * 64;
    const int n0 = blockIdx.x * 64;
    const int t  = threadIdx.x;
    const int tx = t & 15;         // n micro index
    const int ty = t >> 4;         // o micro index
    const float* xb = x + (size_t)b * CC * NSEQ;

    float acc[4][4];
#pragma unroll
    for (int i = 0; i < 4; i++)
#pragma unroll
        for (int j = 0; j < 4; j++) acc[i][j] = 0.f;

    const int wo  = t >> 2;          // 0..63
    const int wc4 = (t & 3) * 4;     // 0,4,8,12
    const int oo  = o0 + wo;
    const float* wrow;
    if (oo < 64)        wrow = wq + (size_t)oo * CC;
    else if (oo < 128)  wrow = wk + (size_t)(oo - 64) * CC;
    else                wrow = wv + (size_t)(oo - 128) * CC;

    const int xc  = t >> 4;          // 0..15
    const int xn4 = (t & 15) * 4;

    for (int c0 = 0; c0 < CC; c0 += 16) {
        float4 w4 = *(const float4*)(wrow + c0 + wc4);
        float4 x4 = *(const float4*)(xb + (size_t)(c0 + xc) * NSEQ + n0 + xn4);
        __syncthreads();
        ws[wc4 + 0][wo] = w4.x; ws[wc4 + 1][wo] = w4.y;
        ws[wc4 + 2][wo] = w4.z; ws[wc4 + 3][wo] = w4.w;
        *(float4*)&xs[xc][xn4] = x4;
        __syncthreads();
#pragma unroll
        for (int c = 0; c < 16; c++) {
            float4 a4 = *(const float4*)&ws[c][4 * ty];
            float4 b4 = *(const float4*)&xs[c][4 * tx];
            float a[4] = {a4.x, a4.y, a4.z, a4.w};
            float bv2[4] = {b4.x, b4.y, b4.z, b4.w};
#pragma unroll
            for (int i = 0; i < 4; i++)
#pragma unroll
                for (int j = 0; j < 4; j++)
                    acc[i][j] = fmaf(a[i], bv2[j], acc[i][j]);
        }
    }

#pragma unroll
    for (int mi = 0; mi < 4; mi++) {
        int o = o0 + 4 * ty + mi;
        float bias; float* dst;
        if (o < 64)       { bias = bq[o];       dst = g_q + ((size_t)b * DQK + o) * NSEQ; }
        else if (o < 128) { bias = bk[o - 64];  dst = g_k + ((size_t)b * DQK + (o - 64)) * NSEQ; }
        else              { bias = bv[o - 128]; dst = g_v + ((size_t)b * CC  + (o - 128)) * NSEQ; }
        float4 r;
        r.x = acc[mi][0] + bias; r.y = acc[mi][1] + bias;
        r.z = acc[mi][2] + bias; r.w = acc[mi][3] + bias;
        *(float4*)(dst + n0 + 4 * tx) = r;
    }
}

// ---------------- pass 2: softmax row stats (online max/sumexp) -------------
__global__ __launch_bounds__(256) void stats_kernel()
{
    __shared__ float qs[DQK][64];
    __shared__ float ks[DQK][64];
    __shared__ float red[2][64][16];

    const int b  = blockIdx.y;
    const int i0 = blockIdx.x * 64;
    const int t  = threadIdx.x;
    const int tx = t & 15;   // j micro
    const int ty = t >> 4;   // i micro

#pragma unroll
    for (int r = 0; r < 4; r++) {
        int idx = t + r * 256;
        int d = idx >> 4, i4 = (idx & 15) * 4;
        *(float4*)&qs[d][i4] = *(const float4*)(g_q + ((size_t)b * DQK + d) * NSEQ + i0 + i4);
    }

    float m[4], l[4];
#pragma unroll
    for (int r = 0; r < 4; r++) { m[r] = -1e30f; l[r] = 0.f; }

    for (int j0 = 0; j0 < NSEQ; j0 += 64) {
        __syncthreads();
#pragma unroll
        for (int r = 0; r < 4; r++) {
            int idx = t + r * 256;
            int d = idx >> 4, j4 = (idx & 15) * 4;
            *(float4*)&ks[d][j4] = *(const float4*)(g_k + ((size_t)b * DQK + d) * NSEQ + j0 + j4);
        }
        __syncthreads();

        float s[4][4];
#pragma unroll
        for (int i = 0; i < 4; i++)
#pragma unroll
            for (int j = 0; j < 4; j++) s[i][j] = 0.f;
#pragma unroll 8
        for (int d = 0; d < DQK; d++) {
            float4 a4 = *(const float4*)&qs[d][4 * ty];
            float4 b4 = *(const float4*)&ks[d][4 * tx];
            float a[4] = {a4.x, a4.y, a4.z, a4.w};
            float bb[4] = {b4.x, b4.y, b4.z, b4.w};
#pragma unroll
            for (int i = 0; i < 4; i++)
#pragma unroll
                for (int j = 0; j < 4; j++)
                    s[i][j] = fmaf(a[i], bb[j], s[i][j]);
        }
#pragma unroll
        for (int ii = 0; ii < 4; ii++) {
            float tm = fmaxf(fmaxf(s[ii][0], s[ii][1]), fmaxf(s[ii][2], s[ii][3]));
            float mn = fmaxf(m[ii], tm);
            float corr = exp2_fast((m[ii] - mn) * LOG2E);
            float add = exp2_fast((s[ii][0] - mn) * LOG2E)
                      + exp2_fast((s[ii][1] - mn) * LOG2E)
                      + exp2_fast((s[ii][2] - mn) * LOG2E)
                      + exp2_fast((s[ii][3] - mn) * LOG2E);
            l[ii] = fmaf(l[ii], corr, add);
            m[ii] = mn;
        }
    }

    __syncthreads();
#pragma unroll
    for (int ii = 0; ii < 4; ii++) {
        red[0][4 * ty + ii][tx] = m[ii];
        red[1][4 * ty + ii][tx] = l[ii];
    }
    __syncthreads();
    if (t < 64) {
        float M = -1e30f;
#pragma unroll
        for (int xk = 0; xk < 16; xk++) M = fmaxf(M, red[0][t][xk]);
        float L = 0.f;
#pragma unroll
        for (int xk = 0; xk < 16; xk++)
            L += red[1][t][xk] * exp2_fast((red[0][t][xk] - M) * LOG2E);
        g_msc[b * NSEQ + i0 + t]  = M * LOG2E;
        g_linv[b * NSEQ + i0 + t] = 1.0f / L;
    }
}

// ---------------- pass 3: out[c,i] = (1/l_i) sum_j v[c,j] exp(s_ij - m_i) ---
// tiles: 64 i x 128 c per block, loop j in 64-chunks, recompute s on the fly.
#define OUT_QS   0
#define OUT_KS   (64 * 64)
#define OUT_PS   (OUT_KS + 64 * 64)            // [j][i], stride 68
#define OUT_VS   (OUT_PS + 64 * 68)            // [j][c], stride 132
#define OUT_MSC  (OUT_VS + 64 * 132)
#define OUT_SMEM_FLOATS (OUT_MSC + 64)
#define OUT_SMEM_BYTES  (OUT_SMEM_FLOATS * 4)

__global__ __launch_bounds__(256) void out_kernel(float* __restrict__ out)
{
    extern __shared__ float sm[];
    float* qs  = sm + OUT_QS;
    float* ks  = sm + OUT_KS;
    float* ps  = sm + OUT_PS;
    float* vs  = sm + OUT_VS;
    float* msc = sm + OUT_MSC;

    const int b  = blockIdx.z;
    const int i0 = blockIdx.x * 64;
    const int c0 = blockIdx.y * 128;
    const int t  = threadIdx.x;
    const int tx = t & 15;   // GEMM1: j micro
    const int ty = t >> 4;   // GEMM1: i micro
    const int i2 = t & 15;   // GEMM2: i micro (4*i2)
    const int ci = t >> 4;   // GEMM2: c micro (8*ci)

#pragma unroll
    for (int r = 0; r < 4; r++) {
        int idx = t + r * 256;
        int d = idx >> 4, i4 = (idx & 15) * 4;
        *(float4*)&qs[d * 64 + i4] = *(const float4*)(g_q + ((size_t)b * DQK + d) * NSEQ + i0 + i4);
    }
    if (t < 64) msc[t] = g_msc[b * NSEQ + i0 + t];

    float acc[8][4];
#pragma unroll
    for (int r = 0; r < 8; r++)
#pragma unroll
        for (int k = 0; k < 4; k++) acc[r][k] = 0.f;

    for (int j0 = 0; j0 < NSEQ; j0 += 64) {
        __syncthreads();   // prev GEMM2 done; also first-iter qs/msc visibility
        // load k tile [d][j]
#pragma unroll
        for (int r = 0; r < 4; r++) {
            int idx = t + r * 256;
            int d = idx >> 4, j4 = (idx & 15) * 4;
            *(float4*)&ks[d * 64 + j4] = *(const float4*)(g_k + ((size_t)b * DQK + d) * NSEQ + j0 + j4);
        }
        // load v tile transposed -> vs[j][c]
        {
            int j4 = (t & 15) * 4;
#pragma unroll
            for (int r = 0; r < 8; r++) {
                int c = (t >> 4) + r * 16;
                float4 v4 = *(const float4*)(g_v + ((size_t)b * CC + c0 + c) * NSEQ + j0 + j4);
                vs[(j4 + 0) * 132 + c] = v4.x;
                vs[(j4 + 1) * 132 + c] = v4.y;
                vs[(j4 + 2) * 132 + c] = v4.z;
                vs[(j4 + 3) * 132 + c] = v4.w;
            }
        }
        __syncthreads();

        // GEMM1: s = q^T k  (4i x 4j per thread)
        float s[4][4];
#pragma unroll
        for (int i = 0; i < 4; i++)
#pragma unroll
            for (int j = 0; j < 4; j++) s[i][j] = 0.f;
#pragma unroll 8
        for (int d = 0; d < DQK; d++) {
            float4 a4 = *(const float4*)&qs[d * 64 + 4 * ty];
            float4 b4 = *(const float4*)&ks[d * 64 + 4 * tx];
            float a[4] = {a4.x, a4.y, a4.z, a4.w};
            float bb[4] = {b4.x, b4.y, b4.z, b4.w};
#pragma unroll
            for (int i = 0; i < 4; i++)
#pragma unroll
                for (int j = 0; j < 4; j++)
                    s[i][j] = fmaf(a[i], bb[j], s[i][j]);
        }
        // p = exp(s - m), write transposed ps[j][i] (float4 along i)
        float mv[4];
#pragma unroll
        for (int ii = 0; ii < 4; ii++) mv[ii] = msc[4 * ty + ii];
#pragma unroll
        for (int jj = 0; jj < 4; jj++) {
            float4 pv;
            pv.x = exp2_fast(fmaf(s[0][jj], LOG2E, -mv[0]));
            pv.y = exp2_fast(fmaf(s[1][jj], LOG2E, -mv[1]));
            pv.z = exp2_fast(fmaf(s[2][jj], LOG2E, -mv[2]));
            pv.w = exp2_fast(fmaf(s[3][jj], LOG2E, -mv[3]));
            *(float4*)&ps[(4 * tx + jj) * 68 + 4 * ty] = pv;
        }
        __syncthreads();

        // GEMM2: acc[c,i] += vs[j][c] * ps[j][i]   (8c x 4i per thread)
#pragma unroll 8
        for (int j = 0; j < 64; j++) {
            float4 p4 = *(const float4*)&ps[j * 68 + 4 * i2];
            float4 va = *(const float4*)&vs[j * 132 + 8 * ci];
            float4 vb = *(const float4*)&vs[j * 132 + 8 * ci + 4];
            float pr[4] = {p4.x, p4.y, p4.z, p4.w};
            float vr[8] = {va.x, va.y, va.z, va.w, vb.x, vb.y, vb.z, vb.w};
#pragma unroll
            for (int r = 0; r < 8; r++)
#pragma unroll
                for (int k = 0; k < 4; k++)
                    acc[r][k] = fmaf(vr[r], pr[k], acc[r][k]);
        }
    }

    // epilogue: scale by 1/l and store
    float4 li4 = *(const float4*)(g_linv + b * NSEQ + i0 + 4 * i2);
    float li[4] = {li4.x, li4.y, li4.z, li4.w};
#pragma unroll
    for (int r = 0; r < 8; r++) {
        int c = c0 + 8 * ci + r;
        float4 o4;
        o4.x = acc[r][0] * li[0];
        o4.y = acc[r][1] * li[1];
        o4.z = acc[r][2] * li[2];
        o4.w = acc[r][3] * li[3];
        *(float4*)(out + ((size_t)b * CC + c) * NSEQ + i0 + 4 * i2) = o4;
    }
}

// ---------------- launch ----------------------------------------------------
extern "C" void kernel_launch(void* const* d_in, const int* in_sizes, int n_in,
                              void* d_out, int out_size)
{
    const float* x  = (const float*)d_in[0];
    const float* wq = (const float*)d_in[1];
    const float* bq = (const float*)d_in[2];
    const float* wk = (const float*)d_in[3];
    const float* bk = (const float*)d_in[4];
    const float* wv = (const float*)d_in[5];
    const float* bv = (const float*)d_in[6];
    float* out = (float*)d_out;

    proj_kernel<<<dim3(NSEQ / 64, 640 / 64, BB), 256>>>(x, wq, bq, wk, bk, wv, bv);
    stats_kernel<<<dim3(NSEQ / 64, BB), 256>>>();
    cudaFuncSetAttribute(out_kernel, cudaFuncAttributeMaxDynamicSharedMemorySize, OUT_SMEM_BYTES);
    out_kernel<<<dim3(NSEQ / 64, CC / 128, BB), 256, OUT_SMEM_BYTES>>>(out);
}

// round 3
// speedup vs baseline: 2.1202x; 2.1202x over previous
#include <cuda_runtime.h>
#include <cuda_bf16.h>
#include <cstdint>

#define BB   4
#define CC   512
#define NSEQ 4096
#define DQK  64
#define LOG2E 1.4426950408889634f

// ---------------- scratch (static device globals: allocation-free) ----------
__device__ float g_qf[BB * DQK * NSEQ];                    // [b][d][i] fp32 (stats)
__device__ float g_kf[BB * DQK * NSEQ];                    // [b][d][j] fp32 (stats)
__device__ __nv_bfloat16 g_qh[BB * NSEQ * DQK];            // [b][i][d] hi
__device__ __nv_bfloat16 g_ql[BB * NSEQ * DQK];            // [b][i][d] lo
__device__ __nv_bfloat16 g_kh[BB * NSEQ * DQK];            // [b][j][d] hi
__device__ __nv_bfloat16 g_kl[BB * NSEQ * DQK];            // [b][j][d] lo
__device__ __nv_bfloat16 g_vh[(size_t)BB * CC * NSEQ];     // [b][c][j] hi
__device__ __nv_bfloat16 g_vl[(size_t)BB * CC * NSEQ];     // [b][c][j] lo
__device__ float g_msc[BB * NSEQ];                         // rowmax * LOG2E
__device__ float g_linv[BB * NSEQ];                        // 1 / rowsum

// ---------------- fast exp2-based exp --------------------------------------
__device__ __forceinline__ float exp2_fast(float y) {
    y = fmaxf(y, -120.0f);
    float t = y + 12582912.0f;
    float n = t - 12582912.0f;
    float f = y - n;
    float p = 1.3333558e-3f;
    p = fmaf(p, f, 9.6181291e-3f);
    p = fmaf(p, f, 5.5504109e-2f);
    p = fmaf(p, f, 2.4022651e-1f);
    p = fmaf(p, f, 6.9314718e-1f);
    p = fmaf(p, f, 1.0f);
    int ni = (int)n;
    return __int_as_float(__float_as_int(p) + (ni << 23));
}

__device__ __forceinline__ uint32_t smem_u32(const void* p) {
    uint32_t a;
    asm("{ .reg .u64 t; cvta.to.shared.u64 t, %1; cvt.u32.u64 %0, t; }" : "=r"(a) : "l"(p));
    return a;
}
__device__ __forceinline__ uint32_t pack_bf2(float a, float b) {
    return ((uint32_t)__bfloat16_as_ushort(__float2bfloat16(b)) << 16) |
            (uint32_t)__bfloat16_as_ushort(__float2bfloat16(a));
}

// mma.sync m16n8k16 row.col bf16 -> f32 accumulate in place
__device__ __forceinline__ void mma_bf16(float* c, const uint32_t* a, uint32_t b0, uint32_t b1) {
    asm volatile("mma.sync.aligned.m16n8k16.row.col.f32.bf16.bf16.f32 "
        "{%0,%1,%2,%3}, {%4,%5,%6,%7}, {%8,%9}, {%0,%1,%2,%3};"
        : "+f"(c[0]), "+f"(c[1]), "+f"(c[2]), "+f"(c[3])
        : "r"(a[0]), "r"(a[1]), "r"(a[2]), "r"(a[3]), "r"(b0), "r"(b1));
}
__device__ __forceinline__ void cp16(uint32_t dst, const void* src) {
    asm volatile("cp.async.cg.shared.global [%0], [%1], 16;" :: "r"(dst), "l"(src));
}
#define CP_COMMIT() asm volatile("cp.async.commit_group;" ::: "memory")
#define CP_WAIT1()  asm volatile("cp.async.wait_group 1;" ::: "memory")

__device__ __forceinline__ uint32_t lds32(uint32_t a) {
    uint32_t v; asm volatile("ld.shared.b32 %0, [%1];" : "=r"(v) : "r"(a)); return v;
}

// ---------------- pass 1: QKV projection (SIMT fp32) ------------------------
__global__ __launch_bounds__(256) void proj_kernel(
    const float* __restrict__ x,
    const float* __restrict__ wq, const float* __restrict__ bq,
    const float* __restrict__ wk, const float* __restrict__ bk,
    const float* __restrict__ wv, const float* __restrict__ bv)
{
    __shared__ float ws[16][68];
    __shared__ float xs[16][64];

    const int b  = blockIdx.z;
    const int o0 = blockIdx.y * 64;
    const int n0 = blockIdx.x * 64;
    const int t  = threadIdx.x;
    const int tx = t & 15;
    const int ty = t >> 4;
    const float* xb = x + (size_t)b * CC * NSEQ;

    float acc[4][4];
#pragma unroll
    for (int i = 0; i < 4; i++)
#pragma unroll
        for (int j = 0; j < 4; j++) acc[i][j] = 0.f;

    const int wo  = t >> 2;
    const int wc4 = (t & 3) * 4;
    const int oo  = o0 + wo;
    const float* wrow;
    if (oo < 64)        wrow = wq + (size_t)oo * CC;
    else if (oo < 128)  wrow = wk + (size_t)(oo - 64) * CC;
    else                wrow = wv + (size_t)(oo - 128) * CC;

    const int xc  = t >> 4;
    const int xn4 = (t & 15) * 4;

    for (int c0 = 0; c0 < CC; c0 += 16) {
        float4 w4 = *(const float4*)(wrow + c0 + wc4);
        float4 x4 = *(const float4*)(xb + (size_t)(c0 + xc) * NSEQ + n0 + xn4);
        __syncthreads();
        ws[wc4 + 0][wo] = w4.x; ws[wc4 + 1][wo] = w4.y;
        ws[wc4 + 2][wo] = w4.z; ws[wc4 + 3][wo] = w4.w;
        *(float4*)&xs[xc][xn4] = x4;
        __syncthreads();
#pragma unroll
        for (int c = 0; c < 16; c++) {
            float4 a4 = *(const float4*)&ws[c][4 * ty];
            float4 b4 = *(const float4*)&xs[c][4 * tx];
            float a[4] = {a4.x, a4.y, a4.z, a4.w};
            float bv2[4] = {b4.x, b4.y, b4.z, b4.w};
#pragma unroll
            for (int i = 0; i < 4; i++)
#pragma unroll
                for (int j = 0; j < 4; j++)
                    acc[i][j] = fmaf(a[i], bv2[j], acc[i][j]);
        }
    }

    const int n = n0 + 4 * tx;
#pragma unroll
    for (int mi = 0; mi < 4; mi++) {
        int o = o0 + 4 * ty + mi;
        if (o < 128) {
            int d = o & 63;
            float bias = (o < 64) ? bq[d] : bk[d];
            float v0 = acc[mi][0] + bias, v1 = acc[mi][1] + bias;
            float v2 = acc[mi][2] + bias, v3 = acc[mi][3] + bias;
            float* df = ((o < 64) ? g_qf : g_kf) + ((size_t)(b * DQK + d)) * NSEQ + n;
            float4 r; r.x = v0; r.y = v1; r.z = v2; r.w = v3;
            *(float4*)df = r;
            __nv_bfloat16* dh = ((o < 64) ? g_qh : g_kh) + ((size_t)b * NSEQ + n) * DQK + d;
            __nv_bfloat16* dl = ((o < 64) ? g_ql : g_kl) + ((size_t)b * NSEQ + n) * DQK + d;
            float vs[4] = {v0, v1, v2, v3};
#pragma unroll
            for (int j = 0; j < 4; j++) {
                __nv_bfloat16 h = __float2bfloat16(vs[j]);
                __nv_bfloat16 l = __float2bfloat16(vs[j] - __bfloat162float(h));
                dh[(size_t)j * DQK] = h;
                dl[(size_t)j * DQK] = l;
            }
        } else {
            int c = o - 128;
            float bias = bv[c];
            float v0 = acc[mi][0] + bias, v1 = acc[mi][1] + bias;
            float v2 = acc[mi][2] + bias, v3 = acc[mi][3] + bias;
            __nv_bfloat16 h0 = __float2bfloat16(v0), h1 = __float2bfloat16(v1);
            __nv_bfloat16 h2 = __float2bfloat16(v2), h3 = __float2bfloat16(v3);
            float l0 = v0 - __bfloat162float(h0), l1 = v1 - __bfloat162float(h1);
            float l2 = v2 - __bfloat162float(h2), l3 = v3 - __bfloat162float(h3);
            size_t off = ((size_t)(b * CC + c)) * NSEQ + n;
            uint2 hw, lw;
            hw.x = ((uint32_t)__bfloat16_as_ushort(h1) << 16) | __bfloat16_as_ushort(h0);
            hw.y = ((uint32_t)__bfloat16_as_ushort(h3) << 16) | __bfloat16_as_ushort(h2);
            lw.x = pack_bf2(l0, l1);
            lw.y = pack_bf2(l2, l3);
            *(uint2*)((char*)g_vh + off * 2) = hw;
            *(uint2*)((char*)g_vl + off * 2) = lw;
        }
    }
}

// ---------------- pass 2: softmax row stats (SIMT fp32, exact) --------------
__global__ __launch_bounds__(256) void stats_kernel()
{
    __shared__ float qs[DQK][64];
    __shared__ float ks[DQK][64];
    __shared__ float red[2][64][16];

    const int b  = blockIdx.y;
    const int i0 = blockIdx.x * 64;
    const int t  = threadIdx.x;
    const int tx = t & 15;
    const int ty = t >> 4;

#pragma unroll
    for (int r = 0; r < 4; r++) {
        int idx = t + r * 256;
        int d = idx >> 4, i4 = (idx & 15) * 4;
        *(float4*)&qs[d][i4] = *(const float4*)(g_qf + ((size_t)b * DQK + d) * NSEQ + i0 + i4);
    }

    float m[4], l[4];
#pragma unroll
    for (int r = 0; r < 4; r++) { m[r] = -1e30f; l[r] = 0.f; }

    for (int j0 = 0; j0 < NSEQ; j0 += 64) {
        __syncthreads();
#pragma unroll
        for (int r = 0; r < 4; r++) {
            int idx = t + r * 256;
            int d = idx >> 4, j4 = (idx & 15) * 4;
            *(float4*)&ks[d][j4] = *(const float4*)(g_kf + ((size_t)b * DQK + d) * NSEQ + j0 + j4);
        }
        __syncthreads();

        float s[4][4];
#pragma unroll
        for (int i = 0; i < 4; i++)
#pragma unroll
            for (int j = 0; j < 4; j++) s[i][j] = 0.f;
#pragma unroll 8
        for (int d = 0; d < DQK; d++) {
            float4 a4 = *(const float4*)&qs[d][4 * ty];
            float4 b4 = *(const float4*)&ks[d][4 * tx];
            float a[4] = {a4.x, a4.y, a4.z, a4.w};
            float bb[4] = {b4.x, b4.y, b4.z, b4.w};
#pragma unroll
            for (int i = 0; i < 4; i++)
#pragma unroll
                for (int j = 0; j < 4; j++)
                    s[i][j] = fmaf(a[i], bb[j], s[i][j]);
        }
#pragma unroll
        for (int ii = 0; ii < 4; ii++) {
            float tm = fmaxf(fmaxf(s[ii][0], s[ii][1]), fmaxf(s[ii][2], s[ii][3]));
            float mn = fmaxf(m[ii], tm);
            float corr = exp2_fast((m[ii] - mn) * LOG2E);
            float add = exp2_fast((s[ii][0] - mn) * LOG2E)
                      + exp2_fast((s[ii][1] - mn) * LOG2E)
                      + exp2_fast((s[ii][2] - mn) * LOG2E)
                      + exp2_fast((s[ii][3] - mn) * LOG2E);
            l[ii] = fmaf(l[ii], corr, add);
            m[ii] = mn;
        }
    }

    __syncthreads();
#pragma unroll
    for (int ii = 0; ii < 4; ii++) {
        red[0][4 * ty + ii][tx] = m[ii];
        red[1][4 * ty + ii][tx] = l[ii];
    }
    __syncthreads();
    if (t < 64) {
        float M = -1e30f;
#pragma unroll
        for (int xk = 0; xk < 16; xk++) M = fmaxf(M, red[0][t][xk]);
        float L = 0.f;
#pragma unroll
        for (int xk = 0; xk < 16; xk++)
            L += red[1][t][xk] * exp2_fast((red[0][t][xk] - M) * LOG2E);
        g_msc[b * NSEQ + i0 + t]  = M * LOG2E;
        g_linv[b * NSEQ + i0 + t] = 1.0f / L;
    }
}

// ---------------- pass 3: HMMA flash attention output -----------------------
// block 128 i x 128 c, 8 warps (warp = 16 i rows, all 128 c), j in 64-chunks,
// double-buffered cp.async tiles. SMEM rows padded to 144B (conflict-free).
#define KROW   144
#define SK_H   0
#define SK_L   9216
#define SV_H   18432
#define SV_L   36864
#define TILE_BYTES 55296
#define N_CHUNK (NSEQ / 64)
#define STG_ROW 132
#define OUT_SMEM_BYTES (2 * TILE_BYTES)

__device__ __forceinline__ void issue_tiles(uint32_t tb, int b, int j0, int c0, int t)
{
#pragma unroll
    for (int r = 0; r < 4; r++) {           // K hi+lo: 1024 16B chunks
        int idx = t + r * 256;
        int arr = idx >> 9;
        int row = (idx >> 3) & 63;
        int col = idx & 7;
        const __nv_bfloat16* src = (arr ? g_kl : g_kh) + ((size_t)b * NSEQ + j0 + row) * DQK + col * 8;
        cp16(tb + SK_H + arr * 9216 + row * KROW + col * 16, src);
    }
#pragma unroll
    for (int r = 0; r < 8; r++) {           // V hi+lo: 2048 16B chunks
        int idx = t + r * 256;
        int arr = idx >> 10;
        int row = (idx >> 3) & 127;
        int col = idx & 7;
        const __nv_bfloat16* src = (arr ? g_vl : g_vh) + ((size_t)(b * CC + c0 + row)) * NSEQ + j0 + col * 8;
        cp16(tb + SV_H + arr * 18432 + row * KROW + col * 16, src);
    }
}

__global__ __launch_bounds__(256, 1) void out_kernel(float* __restrict__ out)
{
    extern __shared__ char smem[];
    const uint32_t sb = smem_u32(smem);
    const int b  = blockIdx.z;
    const int i0 = blockIdx.x * 128;
    const int c0 = blockIdx.y * 128;
    const int t  = threadIdx.x;
    const int w  = t >> 5;
    const int lane = t & 31;
    const int g  = lane >> 2;
    const int t4 = lane & 3;
    const int iw = i0 + w * 16;

    // preload Q fragments (hi/lo), loop-invariant
    uint32_t qh[4][4], ql[4][4];
    {
        const __nv_bfloat16* qhp = g_qh + ((size_t)b * NSEQ + iw) * DQK;
        const __nv_bfloat16* qlp = g_ql + ((size_t)b * NSEQ + iw) * DQK;
#pragma unroll
        for (int kt = 0; kt < 4; kt++) {
            int dbase = kt * 16 + 2 * t4;
            qh[kt][0] = *(const uint32_t*)(qhp + (size_t)g * DQK + dbase);
            qh[kt][1] = *(const uint32_t*)(qhp + (size_t)(g + 8) * DQK + dbase);
            qh[kt][2] = *(const uint32_t*)(qhp + (size_t)g * DQK + dbase + 8);
            qh[kt][3] = *(const uint32_t*)(qhp + (size_t)(g + 8) * DQK + dbase + 8);
            ql[kt][0] = *(const uint32_t*)(qlp + (size_t)g * DQK + dbase);
            ql[kt][1] = *(const uint32_t*)(qlp + (size_t)(g + 8) * DQK + dbase);
            ql[kt][2] = *(const uint32_t*)(qlp + (size_t)g * DQK + dbase + 8);
            ql[kt][3] = *(const uint32_t*)(qlp + (size_t)(g + 8) * DQK + dbase + 8);
        }
    }
    const float msc0 = g_msc[b * NSEQ + iw + g];
    const float msc1 = g_msc[b * NSEQ + iw + g + 8];

    float o[16][4];
#pragma unroll
    for (int ct = 0; ct < 16; ct++)
#pragma unroll
        for (int r = 0; r < 4; r++) o[ct][r] = 0.f;

    issue_tiles(sb, b, 0, c0, t);
    CP_COMMIT();

    for (int it = 0; it < N_CHUNK; ++it) {
        if (it + 1 < N_CHUNK)
            issue_tiles(sb + ((it + 1) & 1) * TILE_BYTES, b, (it + 1) * 64, c0, t);
        CP_COMMIT();
        CP_WAIT1();
        __syncthreads();

        const uint32_t tb = sb + (it & 1) * TILE_BYTES;

        // GEMM1 (S = Q K^T, split 3-pass) + softmax + pack P fragments
        uint32_t ph[4][4], pl[4][4];
#pragma unroll
        for (int kt4 = 0; kt4 < 4; kt4++) {
            float s[2][4];
#pragma unroll
            for (int h = 0; h < 2; h++)
#pragma unroll
                for (int r = 0; r < 4; r++) s[h][r] = 0.f;
#pragma unroll
            for (int h = 0; h < 2; h++) {
                int nt = kt4 * 2 + h;
                uint32_t krow = tb + SK_H + (nt * 8 + g) * KROW + 4 * t4;
#pragma unroll
                for (int kd = 0; kd < 4; kd++) {
                    uint32_t kh0 = lds32(krow + kd * 32);
                    uint32_t kh1 = lds32(krow + kd * 32 + 16);
                    uint32_t kl0 = lds32(krow + 9216 + kd * 32);
                    uint32_t kl1 = lds32(krow + 9216 + kd * 32 + 16);
                    mma_bf16(s[h], qh[kd], kh0, kh1);
                    mma_bf16(s[h], qh[kd], kl0, kl1);
                    mma_bf16(s[h], ql[kd], kh0, kh1);
                }
            }
#pragma unroll
            for (int h = 0; h < 2; h++) {
                float p0 = exp2_fast(fmaf(s[h][0], LOG2E, -msc0));
                float p1 = exp2_fast(fmaf(s[h][1], LOG2E, -msc0));
                float p2 = exp2_fast(fmaf(s[h][2], LOG2E, -msc1));
                float p3 = exp2_fast(fmaf(s[h][3], LOG2E, -msc1));
                __nv_bfloat16 b0 = __float2bfloat16(p0), b1 = __float2bfloat16(p1);
                __nv_bfloat16 b2 = __float2bfloat16(p2), b3 = __float2bfloat16(p3);
                ph[kt4][2 * h + 0] = ((uint32_t)__bfloat16_as_ushort(b1) << 16) | __bfloat16_as_ushort(b0);
                ph[kt4][2 * h + 1] = ((uint32_t)__bfloat16_as_ushort(b3) << 16) | __bfloat16_as_ushort(b2);
                pl[kt4][2 * h + 0] = pack_bf2(p0 - __bfloat162float(b0), p1 - __bfloat162float(b1));
                pl[kt4][2 * h + 1] = pack_bf2(p2 - __bfloat162float(b2), p3 - __bfloat162float(b3));
            }
        }

        // GEMM2: O += P V^T (split 3-pass)
#pragma unroll
        for (int ct = 0; ct < 16; ct++) {
            uint32_t vrow = tb + SV_H + (ct * 8 + g) * KROW + 4 * t4;
#pragma unroll
            for (int jt = 0; jt < 4; jt++) {
                uint32_t vh0 = lds32(vrow + jt * 32);
                uint32_t vh1 = lds32(vrow + jt * 32 + 16);
                uint32_t vl0 = lds32(vrow + 18432 + jt * 32);
                uint32_t vl1 = lds32(vrow + 18432 + jt * 32 + 16);
                mma_bf16(o[ct], ph[jt], vh0, vh1);
                mma_bf16(o[ct], pl[jt], vh0, vh1);
                mma_bf16(o[ct], ph[jt], vl0, vl1);
            }
        }
        __syncthreads();
    }

    // epilogue: scale by 1/l, transpose through SMEM staging, coalesced store
    const float li0 = g_linv[b * NSEQ + iw + g];
    const float li1 = g_linv[b * NSEQ + iw + g + 8];
    float* stg = (float*)smem;
    const int il = w * 16 + g;
#pragma unroll
    for (int ct = 0; ct < 16; ct++) {
        int c = ct * 8 + 2 * t4;
        stg[(size_t)c * STG_ROW + il]           = o[ct][0] * li0;
        stg[(size_t)(c + 1) * STG_ROW + il]     = o[ct][1] * li0;
        stg[(size_t)c * STG_ROW + il + 8]       = o[ct][2] * li1;
        stg[(size_t)(c + 1) * STG_ROW + il + 8] = o[ct][3] * li1;
    }
    __syncthreads();
#pragma unroll
    for (int r = 0; r < 16; r++) {
        int fid = t + r * 256;
        int c = fid >> 5, x = fid & 31;
        float4 v = *(const float4*)&stg[(size_t)c * STG_ROW + x * 4];
        *(float4*)(out + ((size_t)(b * CC + c0 + c)) * NSEQ + i0 + x * 4) = v;
    }
}

// ---------------- launch ----------------------------------------------------
extern "C" void kernel_launch(void* const* d_in, const int* in_sizes, int n_in,
                              void* d_out, int out_size)
{
    const float* x  = (const float*)d_in[0];
    const float* wq = (const float*)d_in[1];
    const float* bq = (const float*)d_in[2];
    const float* wk = (const float*)d_in[3];
    const float* bk = (const float*)d_in[4];
    const float* wv = (const float*)d_in[5];
    const float* bv = (const float*)d_in[6];
    float* out = (float*)d_out;

    proj_kernel<<<dim3(NSEQ / 64, 640 / 64, BB), 256>>>(x, wq, bq, wk, bk, wv, bv);
    stats_kernel<<<dim3(NSEQ / 64, BB), 256>>>();
    cudaFuncSetAttribute(out_kernel, cudaFuncAttributeMaxDynamicSharedMemorySize, OUT_SMEM_BYTES);
    out_kernel<<<dim3(NSEQ / 128, CC / 128, BB), 256, OUT_SMEM_BYTES>>>(out);
}

// round 4
// speedup vs baseline: 2.4813x; 1.1703x over previous
#include <cuda_runtime.h>
#include <cuda_bf16.h>
#include <cstdint>

#define BB   4
#define CC   512
#define NSEQ 4096
#define DQK  64
#define LOG2E 1.4426950408889634f

// ---------------- scratch (static device globals: allocation-free) ----------
__device__ __nv_bfloat16 g_qh[BB * NSEQ * DQK];            // [b][i][d] hi
__device__ __nv_bfloat16 g_ql[BB * NSEQ * DQK];            // [b][i][d] lo
__device__ __nv_bfloat16 g_kh[BB * NSEQ * DQK];            // [b][j][d] hi
__device__ __nv_bfloat16 g_kl[BB * NSEQ * DQK];            // [b][j][d] lo
__device__ __nv_bfloat16 g_vh[(size_t)BB * CC * NSEQ];     // [b][c][j] hi
__device__ __nv_bfloat16 g_vl[(size_t)BB * CC * NSEQ];     // [b][c][j] lo

// ---------------- fast exp2 --------------------------------------------------
__device__ __forceinline__ float exp2_fast(float y) {
    y = fmaxf(y, -120.0f);
    float t = y + 12582912.0f;
    float n = t - 12582912.0f;
    float f = y - n;
    float p = 1.3333558e-3f;
    p = fmaf(p, f, 9.6181291e-3f);
    p = fmaf(p, f, 5.5504109e-2f);
    p = fmaf(p, f, 2.4022651e-1f);
    p = fmaf(p, f, 6.9314718e-1f);
    p = fmaf(p, f, 1.0f);
    int ni = (int)n;
    return __int_as_float(__float_as_int(p) + (ni << 23));
}

__device__ __forceinline__ uint32_t smem_u32(const void* p) {
    uint32_t a;
    asm("{ .reg .u64 t; cvta.to.shared.u64 t, %1; cvt.u32.u64 %0, t; }" : "=r"(a) : "l"(p));
    return a;
}
__device__ __forceinline__ uint32_t pack_bf2(float a, float b) {
    return ((uint32_t)__bfloat16_as_ushort(__float2bfloat16(b)) << 16) |
            (uint32_t)__bfloat16_as_ushort(__float2bfloat16(a));
}

// mma.sync m16n8k16 row.col bf16 -> f32 accumulate in place
__device__ __forceinline__ void mma_bf16(float* c, const uint32_t* a, uint32_t b0, uint32_t b1) {
    asm volatile("mma.sync.aligned.m16n8k16.row.col.f32.bf16.bf16.f32 "
        "{%0,%1,%2,%3}, {%4,%5,%6,%7}, {%8,%9}, {%0,%1,%2,%3};"
        : "+f"(c[0]), "+f"(c[1]), "+f"(c[2]), "+f"(c[3])
        : "r"(a[0]), "r"(a[1]), "r"(a[2]), "r"(a[3]), "r"(b0), "r"(b1));
}
__device__ __forceinline__ void cp16(uint32_t dst, const void* src) {
    asm volatile("cp.async.cg.shared.global [%0], [%1], 16;" :: "r"(dst), "l"(src));
}
#define CP_COMMIT() asm volatile("cp.async.commit_group;" ::: "memory")
#define CP_WAIT1()  asm volatile("cp.async.wait_group 1;" ::: "memory")

__device__ __forceinline__ uint32_t lds32(uint32_t a) {
    uint32_t v; asm volatile("ld.shared.b32 %0, [%1];" : "=r"(v) : "r"(a)); return v;
}

// ---------------- pass 1: QKV projection (SIMT fp32) ------------------------
__global__ __launch_bounds__(256) void proj_kernel(
    const float* __restrict__ x,
    const float* __restrict__ wq, const float* __restrict__ bq,
    const float* __restrict__ wk, const float* __restrict__ bk,
    const float* __restrict__ wv, const float* __restrict__ bv)
{
    __shared__ float ws[16][68];
    __shared__ float xs[16][64];

    const int b  = blockIdx.z;
    const int o0 = blockIdx.y * 64;
    const int n0 = blockIdx.x * 64;
    const int t  = threadIdx.x;
    const int tx = t & 15;
    const int ty = t >> 4;
    const float* xb = x + (size_t)b * CC * NSEQ;

    float acc[4][4];
#pragma unroll
    for (int i = 0; i < 4; i++)
#pragma unroll
        for (int j = 0; j < 4; j++) acc[i][j] = 0.f;

    const int wo  = t >> 2;
    const int wc4 = (t & 3) * 4;
    const int oo  = o0 + wo;
    const float* wrow;
    if (oo < 64)        wrow = wq + (size_t)oo * CC;
    else if (oo < 128)  wrow = wk + (size_t)(oo - 64) * CC;
    else                wrow = wv + (size_t)(oo - 128) * CC;

    const int xc  = t >> 4;
    const int xn4 = (t & 15) * 4;

    for (int c0 = 0; c0 < CC; c0 += 16) {
        float4 w4 = *(const float4*)(wrow + c0 + wc4);
        float4 x4 = *(const float4*)(xb + (size_t)(c0 + xc) * NSEQ + n0 + xn4);
        __syncthreads();
        ws[wc4 + 0][wo] = w4.x; ws[wc4 + 1][wo] = w4.y;
        ws[wc4 + 2][wo] = w4.z; ws[wc4 + 3][wo] = w4.w;
        *(float4*)&xs[xc][xn4] = x4;
        __syncthreads();
#pragma unroll
        for (int c = 0; c < 16; c++) {
            float4 a4 = *(const float4*)&ws[c][4 * ty];
            float4 b4 = *(const float4*)&xs[c][4 * tx];
            float a[4] = {a4.x, a4.y, a4.z, a4.w};
            float bv2[4] = {b4.x, b4.y, b4.z, b4.w};
#pragma unroll
            for (int i = 0; i < 4; i++)
#pragma unroll
                for (int j = 0; j < 4; j++)
                    acc[i][j] = fmaf(a[i], bv2[j], acc[i][j]);
        }
    }

    const int n = n0 + 4 * tx;
#pragma unroll
    for (int mi = 0; mi < 4; mi++) {
        int o = o0 + 4 * ty + mi;
        if (o < 128) {
            int d = o & 63;
            float bias = (o < 64) ? bq[d] : bk[d];
            float v0 = acc[mi][0] + bias, v1 = acc[mi][1] + bias;
            float v2 = acc[mi][2] + bias, v3 = acc[mi][3] + bias;
            __nv_bfloat16* dh = ((o < 64) ? g_qh : g_kh) + ((size_t)b * NSEQ + n) * DQK + d;
            __nv_bfloat16* dl = ((o < 64) ? g_ql : g_kl) + ((size_t)b * NSEQ + n) * DQK + d;
            float vs[4] = {v0, v1, v2, v3};
#pragma unroll
            for (int j = 0; j < 4; j++) {
                __nv_bfloat16 h = __float2bfloat16(vs[j]);
                __nv_bfloat16 l = __float2bfloat16(vs[j] - __bfloat162float(h));
                dh[(size_t)j * DQK] = h;
                dl[(size_t)j * DQK] = l;
            }
        } else {
            int c = o - 128;
            float bias = bv[c];
            float v0 = acc[mi][0] + bias, v1 = acc[mi][1] + bias;
            float v2 = acc[mi][2] + bias, v3 = acc[mi][3] + bias;
            __nv_bfloat16 h0 = __float2bfloat16(v0), h1 = __float2bfloat16(v1);
            __nv_bfloat16 h2 = __float2bfloat16(v2), h3 = __float2bfloat16(v3);
            float l0 = v0 - __bfloat162float(h0), l1 = v1 - __bfloat162float(h1);
            float l2 = v2 - __bfloat162float(h2), l3 = v3 - __bfloat162float(h3);
            size_t off = ((size_t)(b * CC + c)) * NSEQ + n;
            uint2 hw, lw;
            hw.x = ((uint32_t)__bfloat16_as_ushort(h1) << 16) | __bfloat16_as_ushort(h0);
            hw.y = ((uint32_t)__bfloat16_as_ushort(h3) << 16) | __bfloat16_as_ushort(h2);
            lw.x = pack_bf2(l0, l1);
            lw.y = pack_bf2(l2, l3);
            *(uint2*)((char*)g_vh + off * 2) = hw;
            *(uint2*)((char*)g_vl + off * 2) = lw;
        }
    }
}

// ---------------- pass 2: HMMA flash attention, frame-0 softmax --------------
// block 128 i x 256 c, 8 warps (warp = 16 i rows, all 256 c), j in 64-chunks,
// double-buffered cp.async tiles. SMEM rows padded to 144B (conflict-free).
#define KROW   144
#define SK_H   0
#define SK_L   9216
#define SV_H   18432
#define SV_L   (18432 + 36864)
#define TILE_BYTES (18432 + 2 * 36864)
#define N_CHUNK (NSEQ / 64)
#define CTILE  256
#define STG_ROW 132
#define OUT_SMEM_BYTES (2 * TILE_BYTES)

__device__ __forceinline__ void issue_tiles(uint32_t tb, int b, int j0, int c0, int t)
{
#pragma unroll
    for (int r = 0; r < 4; r++) {           // K hi+lo: 1024 16B chunks
        int idx = t + r * 256;
        int arr = idx >> 9;
        int row = (idx >> 3) & 63;
        int col = idx & 7;
        const __nv_bfloat16* src = (arr ? g_kl : g_kh) + ((size_t)b * NSEQ + j0 + row) * DQK + col * 8;
        cp16(tb + SK_H + arr * 9216 + row * KROW + col * 16, src);
    }
#pragma unroll
    for (int r = 0; r < 16; r++) {          // V hi+lo: 4096 16B chunks
        int idx = t + r * 256;
        int arr = idx >> 11;
        int row = (idx >> 3) & 255;
        int col = idx & 7;
        const __nv_bfloat16* src = (arr ? g_vl : g_vh) + ((size_t)(b * CC + c0 + row)) * NSEQ + j0 + col * 8;
        cp16(tb + SV_H + arr * 36864 + row * KROW + col * 16, src);
    }
}

__global__ __launch_bounds__(256, 1) void out_kernel(float* __restrict__ out)
{
    extern __shared__ char smem[];
    const uint32_t sb = smem_u32(smem);
    const int b  = blockIdx.z;
    const int i0 = blockIdx.x * 128;
    const int c0 = blockIdx.y * CTILE;
    const int t  = threadIdx.x;
    const int w  = t >> 5;
    const int lane = t & 31;
    const int g  = lane >> 2;
    const int t4 = lane & 3;
    const int iw = i0 + w * 16;

    // preload Q fragments (hi/lo), loop-invariant
    uint32_t qh[4][4], ql[4][4];
    {
        const __nv_bfloat16* qhp = g_qh + ((size_t)b * NSEQ + iw) * DQK;
        const __nv_bfloat16* qlp = g_ql + ((size_t)b * NSEQ + iw) * DQK;
#pragma unroll
        for (int kt = 0; kt < 4; kt++) {
            int dbase = kt * 16 + 2 * t4;
            qh[kt][0] = *(const uint32_t*)(qhp + (size_t)g * DQK + dbase);
            qh[kt][1] = *(const uint32_t*)(qhp + (size_t)(g + 8) * DQK + dbase);
            qh[kt][2] = *(const uint32_t*)(qhp + (size_t)g * DQK + dbase + 8);
            qh[kt][3] = *(const uint32_t*)(qhp + (size_t)(g + 8) * DQK + dbase + 8);
            ql[kt][0] = *(const uint32_t*)(qlp + (size_t)g * DQK + dbase);
            ql[kt][1] = *(const uint32_t*)(qlp + (size_t)(g + 8) * DQK + dbase);
            ql[kt][2] = *(const uint32_t*)(qlp + (size_t)g * DQK + dbase + 8);
            ql[kt][3] = *(const uint32_t*)(qlp + (size_t)(g + 8) * DQK + dbase + 8);
        }
    }

    float o[CTILE / 8][4];
#pragma unroll
    for (int ct = 0; ct < CTILE / 8; ct++)
#pragma unroll
        for (int r = 0; r < 4; r++) o[ct][r] = 0.f;
    float lsum0 = 0.f, lsum1 = 0.f;   // row sums for rows g and g+8 (frame 0)

    issue_tiles(sb, b, 0, c0, t);
    CP_COMMIT();

    for (int it = 0; it < N_CHUNK; ++it) {
        if (it + 1 < N_CHUNK)
            issue_tiles(sb + ((it + 1) & 1) * TILE_BYTES, b, (it + 1) * 64, c0, t);
        CP_COMMIT();
        CP_WAIT1();
        __syncthreads();

        const uint32_t tb = sb + (it & 1) * TILE_BYTES;

        // GEMM1 (S = Q K^T, split 3-pass) + frame-0 softmax + pack P fragments
        uint32_t ph[4][4], pl[4][4];
#pragma unroll
        for (int kt4 = 0; kt4 < 4; kt4++) {
            float s[2][4];
#pragma unroll
            for (int h = 0; h < 2; h++)
#pragma unroll
                for (int r = 0; r < 4; r++) s[h][r] = 0.f;
#pragma unroll
            for (int h = 0; h < 2; h++) {
                int nt = kt4 * 2 + h;
                uint32_t krow = tb + SK_H + (nt * 8 + g) * KROW + 4 * t4;
#pragma unroll
                for (int kd = 0; kd < 4; kd++) {
                    uint32_t kh0 = lds32(krow + kd * 32);
                    uint32_t kh1 = lds32(krow + kd * 32 + 16);
                    uint32_t kl0 = lds32(krow + 9216 + kd * 32);
                    uint32_t kl1 = lds32(krow + 9216 + kd * 32 + 16);
                    mma_bf16(s[h], qh[kd], kh0, kh1);
                    mma_bf16(s[h], qh[kd], kl0, kl1);
                    mma_bf16(s[h], ql[kd], kh0, kh1);
                }
            }
#pragma unroll
            for (int h = 0; h < 2; h++) {
                float p0 = exp2_fast(s[h][0] * LOG2E);
                float p1 = exp2_fast(s[h][1] * LOG2E);
                float p2 = exp2_fast(s[h][2] * LOG2E);
                float p3 = exp2_fast(s[h][3] * LOG2E);
                lsum0 += p0 + p1;
                lsum1 += p2 + p3;
                __nv_bfloat16 b0 = __float2bfloat16(p0), b1 = __float2bfloat16(p1);
                __nv_bfloat16 b2 = __float2bfloat16(p2), b3 = __float2bfloat16(p3);
                ph[kt4][2 * h + 0] = ((uint32_t)__bfloat16_as_ushort(b1) << 16) | __bfloat16_as_ushort(b0);
                ph[kt4][2 * h + 1] = ((uint32_t)__bfloat16_as_ushort(b3) << 16) | __bfloat16_as_ushort(b2);
                pl[kt4][2 * h + 0] = pack_bf2(p0 - __bfloat162float(b0), p1 - __bfloat162float(b1));
                pl[kt4][2 * h + 1] = pack_bf2(p2 - __bfloat162float(b2), p3 - __bfloat162float(b3));
            }
        }

        // GEMM2: O += P V^T (split 3-pass)
#pragma unroll
        for (int ct = 0; ct < CTILE / 8; ct++) {
            uint32_t vrow = tb + SV_H + (ct * 8 + g) * KROW + 4 * t4;
#pragma unroll
            for (int jt = 0; jt < 4; jt++) {
                uint32_t vh0 = lds32(vrow + jt * 32);
                uint32_t vh1 = lds32(vrow + jt * 32 + 16);
                uint32_t vl0 = lds32(vrow + SV_L - SV_H + jt * 32);
                uint32_t vl1 = lds32(vrow + SV_L - SV_H + jt * 32 + 16);
                mma_bf16(o[ct], ph[jt], vh0, vh1);
                mma_bf16(o[ct], pl[jt], vh0, vh1);
                mma_bf16(o[ct], ph[jt], vl0, vl1);
            }
        }
        __syncthreads();
    }

    // reduce row sums across the 4 lanes sharing a row
    lsum0 += __shfl_xor_sync(0xFFFFFFFFu, lsum0, 1);
    lsum0 += __shfl_xor_sync(0xFFFFFFFFu, lsum0, 2);
    lsum1 += __shfl_xor_sync(0xFFFFFFFFu, lsum1, 1);
    lsum1 += __shfl_xor_sync(0xFFFFFFFFu, lsum1, 2);
    const float li0 = 1.0f / lsum0;
    const float li1 = 1.0f / lsum1;

    // epilogue: scale by 1/l, transpose through SMEM staging, coalesced store
    float* stg = (float*)smem;
    const int il = w * 16 + g;
#pragma unroll
    for (int ct = 0; ct < CTILE / 8; ct++) {
        int c = ct * 8 + 2 * t4;
        stg[(size_t)c * STG_ROW + il]           = o[ct][0] * li0;
        stg[(size_t)(c + 1) * STG_ROW + il]     = o[ct][1] * li0;
        stg[(size_t)c * STG_ROW + il + 8]       = o[ct][2] * li1;
        stg[(size_t)(c + 1) * STG_ROW + il + 8] = o[ct][3] * li1;
    }
    __syncthreads();
#pragma unroll
    for (int r = 0; r < CTILE / 8; r++) {
        int fid = t + r * 256;
        int c = fid >> 5, x = fid & 31;
        float4 v = *(const float4*)&stg[(size_t)c * STG_ROW + x * 4];
        *(float4*)(out + ((size_t)(b * CC + c0 + c)) * NSEQ + i0 + x * 4) = v;
    }
}

// ---------------- launch ----------------------------------------------------
extern "C" void kernel_launch(void* const* d_in, const int* in_sizes, int n_in,
                              void* d_out, int out_size)
{
    const float* x  = (const float*)d_in[0];
    const float* wq = (const float*)d_in[1];
    const float* bq = (const float*)d_in[2];
    const float* wk = (const float*)d_in[3];
    const float* bk = (const float*)d_in[4];
    const float* wv = (const float*)d_in[5];
    const float* bv = (const float*)d_in[6];
    float* out = (float*)d_out;

    proj_kernel<<<dim3(NSEQ / 64, 640 / 64, BB), 256>>>(x, wq, bq, wk, bk, wv, bv);
    cudaFuncSetAttribute(out_kernel, cudaFuncAttributeMaxDynamicSharedMemorySize, OUT_SMEM_BYTES);
    out_kernel<<<dim3(NSEQ / 128, CC / CTILE, BB), 256, OUT_SMEM_BYTES>>>(out);
}

// round 5
// speedup vs baseline: 3.6381x; 1.4662x over previous
#include <cuda_runtime.h>
#include <cuda_fp16.h>
#include <cstdint>

#define BB   4
#define CC   512
#define NSEQ 4096
#define DQK  64
#define LOG2E 1.4426950408889634f

// ---------------- scratch (static device globals: allocation-free) ----------
__device__ __half g_qh[BB * NSEQ * DQK];            // [b][i][d] hi
__device__ __half g_ql[BB * NSEQ * DQK];            // [b][i][d] lo
__device__ __half g_kh[BB * NSEQ * DQK];            // [b][j][d] hi
__device__ __half g_kl[BB * NSEQ * DQK];            // [b][j][d] lo
__device__ __half g_v [(size_t)BB * CC * NSEQ];     // [b][c][j] single fp16

// ---------------- fast exp2 --------------------------------------------------
__device__ __forceinline__ float exp2_fast(float y) {
    y = fmaxf(y, -120.0f);
    float t = y + 12582912.0f;
    float n = t - 12582912.0f;
    float f = y - n;
    float p = 1.3333558e-3f;
    p = fmaf(p, f, 9.6181291e-3f);
    p = fmaf(p, f, 5.5504109e-2f);
    p = fmaf(p, f, 2.4022651e-1f);
    p = fmaf(p, f, 6.9314718e-1f);
    p = fmaf(p, f, 1.0f);
    int ni = (int)n;
    return __int_as_float(__float_as_int(p) + (ni << 23));
}

__device__ __forceinline__ uint32_t smem_u32(const void* p) {
    uint32_t a;
    asm("{ .reg .u64 t; cvta.to.shared.u64 t, %1; cvt.u32.u64 %0, t; }" : "=r"(a) : "l"(p));
    return a;
}
__device__ __forceinline__ uint32_t pack_h2(float a, float b) {
    __half2 h = __floats2half2_rn(a, b);
    return *(uint32_t*)&h;
}

// mma.sync m16n8k16 row.col fp16 -> f32 accumulate in place
__device__ __forceinline__ void mma_f16(float* c, const uint32_t* a, uint32_t b0, uint32_t b1) {
    asm volatile("mma.sync.aligned.m16n8k16.row.col.f32.f16.f16.f32 "
        "{%0,%1,%2,%3}, {%4,%5,%6,%7}, {%8,%9}, {%0,%1,%2,%3};"
        : "+f"(c[0]), "+f"(c[1]), "+f"(c[2]), "+f"(c[3])
        : "r"(a[0]), "r"(a[1]), "r"(a[2]), "r"(a[3]), "r"(b0), "r"(b1));
}
__device__ __forceinline__ void ldsm4(uint32_t* r, uint32_t a) {
    asm volatile("ldmatrix.sync.aligned.m8n8.x4.shared.b16 {%0,%1,%2,%3}, [%4];"
        : "=r"(r[0]), "=r"(r[1]), "=r"(r[2]), "=r"(r[3]) : "r"(a));
}
__device__ __forceinline__ void cp16(uint32_t dst, const void* src) {
    asm volatile("cp.async.cg.shared.global [%0], [%1], 16;" :: "r"(dst), "l"(src));
}
#define CP_COMMIT() asm volatile("cp.async.commit_group;" ::: "memory")
#define CP_WAIT1()  asm volatile("cp.async.wait_group 1;" ::: "memory")

// ---------------- pass 1: QKV projection (SIMT fp32) ------------------------
__global__ __launch_bounds__(256) void proj_kernel(
    const float* __restrict__ x,
    const float* __restrict__ wq, const float* __restrict__ bq,
    const float* __restrict__ wk, const float* __restrict__ bk,
    const float* __restrict__ wv, const float* __restrict__ bv)
{
    __shared__ float ws[16][68];
    __shared__ float xs[16][64];

    const int b  = blockIdx.z;
    const int o0 = blockIdx.y * 64;
    const int n0 = blockIdx.x * 64;
    const int t  = threadIdx.x;
    const int tx = t & 15;
    const int ty = t >> 4;
    const float* xb = x + (size_t)b * CC * NSEQ;

    float acc[4][4];
#pragma unroll
    for (int i = 0; i < 4; i++)
#pragma unroll
        for (int j = 0; j < 4; j++) acc[i][j] = 0.f;

    const int wo  = t >> 2;
    const int wc4 = (t & 3) * 4;
    const int oo  = o0 + wo;
    const float* wrow;
    if (oo < 64)        wrow = wq + (size_t)oo * CC;
    else if (oo < 128)  wrow = wk + (size_t)(oo - 64) * CC;
    else                wrow = wv + (size_t)(oo - 128) * CC;

    const int xc  = t >> 4;
    const int xn4 = (t & 15) * 4;

    for (int c0 = 0; c0 < CC; c0 += 16) {
        float4 w4 = *(const float4*)(wrow + c0 + wc4);
        float4 x4 = *(const float4*)(xb + (size_t)(c0 + xc) * NSEQ + n0 + xn4);
        __syncthreads();
        ws[wc4 + 0][wo] = w4.x; ws[wc4 + 1][wo] = w4.y;
        ws[wc4 + 2][wo] = w4.z; ws[wc4 + 3][wo] = w4.w;
        *(float4*)&xs[xc][xn4] = x4;
        __syncthreads();
#pragma unroll
        for (int c = 0; c < 16; c++) {
            float4 a4 = *(const float4*)&ws[c][4 * ty];
            float4 b4 = *(const float4*)&xs[c][4 * tx];
            float a[4] = {a4.x, a4.y, a4.z, a4.w};
            float bv2[4] = {b4.x, b4.y, b4.z, b4.w};
#pragma unroll
            for (int i = 0; i < 4; i++)
#pragma unroll
                for (int j = 0; j < 4; j++)
                    acc[i][j] = fmaf(a[i], bv2[j], acc[i][j]);
        }
    }

    const int n = n0 + 4 * tx;
#pragma unroll
    for (int mi = 0; mi < 4; mi++) {
        int o = o0 + 4 * ty + mi;
        if (o < 128) {
            int d = o & 63;
            float bias = (o < 64) ? bq[d] : bk[d];
            __half* dh = ((o < 64) ? g_qh : g_kh) + ((size_t)b * NSEQ + n) * DQK + d;
            __half* dl = ((o < 64) ? g_ql : g_kl) + ((size_t)b * NSEQ + n) * DQK + d;
            float vs[4] = {acc[mi][0] + bias, acc[mi][1] + bias,
                           acc[mi][2] + bias, acc[mi][3] + bias};
#pragma unroll
            for (int j = 0; j < 4; j++) {
                __half h = __float2half_rn(vs[j]);
                __half l = __float2half_rn(vs[j] - __half2float(h));
                dh[(size_t)j * DQK] = h;
                dl[(size_t)j * DQK] = l;
            }
        } else {
            int c = o - 128;
            float bias = bv[c];
            size_t off = ((size_t)(b * CC + c)) * NSEQ + n;
            uint2 w2;
            w2.x = pack_h2(acc[mi][0] + bias, acc[mi][1] + bias);
            w2.y = pack_h2(acc[mi][2] + bias, acc[mi][3] + bias);
            *(uint2*)((char*)g_v + off * 2) = w2;
        }
    }
}

// ---------------- pass 2: HMMA fp16 flash attention (online rescale) ---------
// block 128 i x 128 c, 8 warps (warp = 16 i rows, all 128 c), j in 64-chunks,
// double-buffered cp.async tiles. Row pitch 144B; ldmatrix fragment loads.
#define KROW   144
#define SK_H   0
#define SK_L   9216
#define SV     18432
#define TILE_BYTES 36864
#define N_CHUNK (NSEQ / 64)
#define CTILE  128
#define STG_ROW 132
#define OUT_SMEM_BYTES (2 * TILE_BYTES)

__device__ __forceinline__ void issue_tiles(uint32_t tb, int b, int j0, int c0, int t)
{
#pragma unroll
    for (int r = 0; r < 4; r++) {           // K hi+lo: 1024 16B chunks
        int idx = t + r * 256;
        int arr = idx >> 9;
        int row = (idx >> 3) & 63;
        int col = idx & 7;
        const __half* src = (arr ? g_kl : g_kh) + ((size_t)b * NSEQ + j0 + row) * DQK + col * 8;
        cp16(tb + SK_H + arr * 9216 + row * KROW + col * 16, src);
    }
#pragma unroll
    for (int r = 0; r < 4; r++) {           // V single: 1024 16B chunks
        int idx = t + r * 256;
        int row = (idx >> 3) & 127;
        int col = idx & 7;
        const __half* src = g_v + ((size_t)(b * CC + c0 + row)) * NSEQ + j0 + col * 8;
        cp16(tb + SV + row * KROW + col * 16, src);
    }
}

__global__ __launch_bounds__(256, 1) void out_kernel(float* __restrict__ out)
{
    extern __shared__ char smem[];
    const uint32_t sb = smem_u32(smem);
    const int b  = blockIdx.z;
    const int i0 = blockIdx.x * 128;
    const int c0 = blockIdx.y * CTILE;
    const int t  = threadIdx.x;
    const int w  = t >> 5;
    const int lane = t & 31;
    const int g  = lane >> 2;
    const int t4 = lane & 3;
    const int l8 = lane & 7;
    const int tt = lane >> 3;
    const int iw = i0 + w * 16;

    // preload Q fragments (hi/lo), loop-invariant
    uint32_t qh[4][4], ql[4][4];
    {
        const __half* qhp = g_qh + ((size_t)b * NSEQ + iw) * DQK;
        const __half* qlp = g_ql + ((size_t)b * NSEQ + iw) * DQK;
#pragma unroll
        for (int kt = 0; kt < 4; kt++) {
            int dbase = kt * 16 + 2 * t4;
            qh[kt][0] = *(const uint32_t*)(qhp + (size_t)g * DQK + dbase);
            qh[kt][1] = *(const uint32_t*)(qhp + (size_t)(g + 8) * DQK + dbase);
            qh[kt][2] = *(const uint32_t*)(qhp + (size_t)g * DQK + dbase + 8);
            qh[kt][3] = *(const uint32_t*)(qhp + (size_t)(g + 8) * DQK + dbase + 8);
            ql[kt][0] = *(const uint32_t*)(qlp + (size_t)g * DQK + dbase);
            ql[kt][1] = *(const uint32_t*)(qlp + (size_t)(g + 8) * DQK + dbase);
            ql[kt][2] = *(const uint32_t*)(qlp + (size_t)g * DQK + dbase + 8);
            ql[kt][3] = *(const uint32_t*)(qlp + (size_t)(g + 8) * DQK + dbase + 8);
        }
    }

    float o[CTILE / 8][4];
#pragma unroll
    for (int ct = 0; ct < CTILE / 8; ct++)
#pragma unroll
        for (int r = 0; r < 4; r++) o[ct][r] = 0.f;
    float m0 = -1e30f, m1 = -1e30f;     // running row max (log2 units)
    float lsum0 = 0.f, lsum1 = 0.f;     // row sums in current frame

    issue_tiles(sb, b, 0, c0, t);
    CP_COMMIT();

    for (int it = 0; it < N_CHUNK; ++it) {
        if (it + 1 < N_CHUNK)
            issue_tiles(sb + ((it + 1) & 1) * TILE_BYTES, b, (it + 1) * 64, c0, t);
        CP_COMMIT();
        CP_WAIT1();
        __syncthreads();

        const uint32_t tb = sb + (it & 1) * TILE_BYTES;

        // ---- GEMM1: S = Q K^T (fp16 split-3) ----
        float s[4][2][4];
#pragma unroll
        for (int kt4 = 0; kt4 < 4; kt4++) {
#pragma unroll
            for (int h = 0; h < 2; h++) {
#pragma unroll
                for (int r = 0; r < 4; r++) s[kt4][h][r] = 0.f;
                int nt = kt4 * 2 + h;
                uint32_t krow = tb + (nt * 8 + l8) * KROW + tt * 16;
#pragma unroll
                for (int kp = 0; kp < 2; kp++) {
                    uint32_t kh[4], kl[4];
                    ldsm4(kh, krow + SK_H + kp * 64);
                    ldsm4(kl, krow + SK_L + kp * 64);
                    mma_f16(s[kt4][h], qh[2 * kp],     kh[0], kh[1]);
                    mma_f16(s[kt4][h], qh[2 * kp + 1], kh[2], kh[3]);
                    mma_f16(s[kt4][h], ql[2 * kp],     kh[0], kh[1]);
                    mma_f16(s[kt4][h], ql[2 * kp + 1], kh[2], kh[3]);
                    mma_f16(s[kt4][h], qh[2 * kp],     kl[0], kl[1]);
                    mma_f16(s[kt4][h], qh[2 * kp + 1], kl[2], kl[3]);
                }
            }
        }

        // ---- online rescale: chunk max -> update frame ----
        float cm0 = -1e30f, cm1 = -1e30f;
#pragma unroll
        for (int kt4 = 0; kt4 < 4; kt4++)
#pragma unroll
            for (int h = 0; h < 2; h++) {
                cm0 = fmaxf(cm0, fmaxf(s[kt4][h][0], s[kt4][h][1]));
                cm1 = fmaxf(cm1, fmaxf(s[kt4][h][2], s[kt4][h][3]));
            }
        cm0 = fmaxf(cm0, __shfl_xor_sync(0xFFFFFFFFu, cm0, 1));
        cm0 = fmaxf(cm0, __shfl_xor_sync(0xFFFFFFFFu, cm0, 2));
        cm1 = fmaxf(cm1, __shfl_xor_sync(0xFFFFFFFFu, cm1, 1));
        cm1 = fmaxf(cm1, __shfl_xor_sync(0xFFFFFFFFu, cm1, 2));
        float m0n = fmaxf(m0, cm0 * LOG2E);
        float m1n = fmaxf(m1, cm1 * LOG2E);
        float f0 = exp2_fast(m0 - m0n);
        float f1 = exp2_fast(m1 - m1n);
        m0 = m0n; m1 = m1n;
        lsum0 *= f0; lsum1 *= f1;
#pragma unroll
        for (int ct = 0; ct < CTILE / 8; ct++) {
            o[ct][0] *= f0; o[ct][1] *= f0;
            o[ct][2] *= f1; o[ct][3] *= f1;
        }

        // ---- softmax exp + pack P (fp16, <=1) ----
        uint32_t pa[4][4];
#pragma unroll
        for (int kt4 = 0; kt4 < 4; kt4++)
#pragma unroll
            for (int h = 0; h < 2; h++) {
                float p0 = exp2_fast(fmaf(s[kt4][h][0], LOG2E, -m0));
                float p1 = exp2_fast(fmaf(s[kt4][h][1], LOG2E, -m0));
                float p2 = exp2_fast(fmaf(s[kt4][h][2], LOG2E, -m1));
                float p3 = exp2_fast(fmaf(s[kt4][h][3], LOG2E, -m1));
                lsum0 += p0 + p1;
                lsum1 += p2 + p3;
                pa[kt4][2 * h + 0] = pack_h2(p0, p1);
                pa[kt4][2 * h + 1] = pack_h2(p2, p3);
            }

        // ---- GEMM2: O += P V^T (fp16 single) ----
#pragma unroll
        for (int ct = 0; ct < CTILE / 8; ct++) {
            uint32_t vrow = tb + SV + (ct * 8 + l8) * KROW + tt * 16;
#pragma unroll
            for (int jh = 0; jh < 2; jh++) {
                uint32_t vv[4];
                ldsm4(vv, vrow + jh * 64);
                mma_f16(o[ct], pa[2 * jh],     vv[0], vv[1]);
                mma_f16(o[ct], pa[2 * jh + 1], vv[2], vv[3]);
            }
        }
        __syncthreads();
    }

    // reduce row sums across the 4 lanes sharing a row (same frame: m is row-uniform)
    lsum0 += __shfl_xor_sync(0xFFFFFFFFu, lsum0, 1);
    lsum0 += __shfl_xor_sync(0xFFFFFFFFu, lsum0, 2);
    lsum1 += __shfl_xor_sync(0xFFFFFFFFu, lsum1, 1);
    lsum1 += __shfl_xor_sync(0xFFFFFFFFu, lsum1, 2);
    const float li0 = 1.0f / lsum0;
    const float li1 = 1.0f / lsum1;

    // epilogue: scale by 1/l, transpose through SMEM staging, coalesced store
    float* stg = (float*)smem;
    const int il = w * 16 + g;
#pragma unroll
    for (int ct = 0; ct < CTILE / 8; ct++) {
        int c = ct * 8 + 2 * t4;
        stg[(size_t)c * STG_ROW + il]           = o[ct][0] * li0;
        stg[(size_t)(c + 1) * STG_ROW + il]     = o[ct][1] * li0;
        stg[(size_t)c * STG_ROW + il + 8]       = o[ct][2] * li1;
        stg[(size_t)(c + 1) * STG_ROW + il + 8] = o[ct][3] * li1;
    }
    __syncthreads();
#pragma unroll
    for (int r = 0; r < CTILE / 8; r++) {
        int fid = t + r * 256;
        int c = fid >> 5, x = fid & 31;
        float4 v = *(const float4*)&stg[(size_t)c * STG_ROW + x * 4];
        *(float4*)(out + ((size_t)(b * CC + c0 + c)) * NSEQ + i0 + x * 4) = v;
    }
}

// ---------------- launch ----------------------------------------------------
extern "C" void kernel_launch(void* const* d_in, const int* in_sizes, int n_in,
                              void* d_out, int out_size)
{
    const float* x  = (const float*)d_in[0];
    const float* wq = (const float*)d_in[1];
    const float* bq = (const float*)d_in[2];
    const float* wk = (const float*)d_in[3];
    const float* bk = (const float*)d_in[4];
    const float* wv = (const float*)d_in[5];
    const float* bv = (const float*)d_in[6];
    float* out = (float*)d_out;

    proj_kernel<<<dim3(NSEQ / 64, 640 / 64, BB), 256>>>(x, wq, bq, wk, bk, wv, bv);
    cudaFuncSetAttribute(out_kernel, cudaFuncAttributeMaxDynamicSharedMemorySize, OUT_SMEM_BYTES);
    out_kernel<<<dim3(NSEQ / 128, CC / CTILE, BB), 256, OUT_SMEM_BYTES>>>(out);
}

// round 6
// speedup vs baseline: 4.4061x; 1.2111x over previous
#include <cuda_runtime.h>
#include <cuda_fp16.h>
#include <cstdint>

#define BB   4
#define CC   512
#define NSEQ 4096
#define DQK  64
#define LOG2E 1.4426950408889634f

// ---------------- scratch (static device globals: allocation-free) ----------
__device__ __half g_qh[BB * NSEQ * DQK];            // [b][i][d] hi
__device__ __half g_ql[BB * NSEQ * DQK];            // [b][i][d] lo
__device__ __half g_kh[BB * NSEQ * DQK];            // [b][j][d] hi
__device__ __half g_kl[BB * NSEQ * DQK];            // [b][j][d] lo
__device__ __half g_v [(size_t)BB * CC * NSEQ];     // [b][c][j] single fp16

// ---------------- fast exp2 --------------------------------------------------
__device__ __forceinline__ float exp2_fast(float y) {
    y = fmaxf(y, -120.0f);
    float t = y + 12582912.0f;
    float n = t - 12582912.0f;
    float f = y - n;
    float p = 1.3333558e-3f;
    p = fmaf(p, f, 9.6181291e-3f);
    p = fmaf(p, f, 5.5504109e-2f);
    p = fmaf(p, f, 2.4022651e-1f);
    p = fmaf(p, f, 6.9314718e-1f);
    p = fmaf(p, f, 1.0f);
    int ni = (int)n;
    return __int_as_float(__float_as_int(p) + (ni << 23));
}

__device__ __forceinline__ uint32_t smem_u32(const void* p) {
    uint32_t a;
    asm("{ .reg .u64 t; cvta.to.shared.u64 t, %1; cvt.u32.u64 %0, t; }" : "=r"(a) : "l"(p));
    return a;
}
__device__ __forceinline__ uint32_t pack_h2(float a, float b) {
    __half2 h = __floats2half2_rn(a, b);
    return *(uint32_t*)&h;
}

// mma.sync m16n8k16 row.col fp16 -> f32 accumulate in place
__device__ __forceinline__ void mma_f16(float* c, const uint32_t* a, uint32_t b0, uint32_t b1) {
    asm volatile("mma.sync.aligned.m16n8k16.row.col.f32.f16.f16.f32 "
        "{%0,%1,%2,%3}, {%4,%5,%6,%7}, {%8,%9}, {%0,%1,%2,%3};"
        : "+f"(c[0]), "+f"(c[1]), "+f"(c[2]), "+f"(c[3])
        : "r"(a[0]), "r"(a[1]), "r"(a[2]), "r"(a[3]), "r"(b0), "r"(b1));
}
__device__ __forceinline__ void ldsm4(uint32_t* r, uint32_t a) {
    asm volatile("ldmatrix.sync.aligned.m8n8.x4.shared.b16 {%0,%1,%2,%3}, [%4];"
        : "=r"(r[0]), "=r"(r[1]), "=r"(r[2]), "=r"(r[3]) : "r"(a));
}
__device__ __forceinline__ void cp16(uint32_t dst, const void* src) {
    asm volatile("cp.async.cg.shared.global [%0], [%1], 16;" :: "r"(dst), "l"(src));
}
#define CP_COMMIT() asm volatile("cp.async.commit_group;" ::: "memory")
#define CP_WAIT1()  asm volatile("cp.async.wait_group 1;" ::: "memory")

// ---------------- pass 1: QKV projection (SIMT fp32) ------------------------
__global__ __launch_bounds__(256) void proj_kernel(
    const float* __restrict__ x,
    const float* __restrict__ wq, const float* __restrict__ bq,
    const float* __restrict__ wk, const float* __restrict__ bk,
    const float* __restrict__ wv, const float* __restrict__ bv)
{
    __shared__ float ws[16][68];
    __shared__ float xs[16][64];

    const int b  = blockIdx.z;
    const int o0 = blockIdx.y * 64;
    const int n0 = blockIdx.x * 64;
    const int t  = threadIdx.x;
    const int tx = t & 15;
    const int ty = t >> 4;
    const float* xb = x + (size_t)b * CC * NSEQ;

    float acc[4][4];
#pragma unroll
    for (int i = 0; i < 4; i++)
#pragma unroll
        for (int j = 0; j < 4; j++) acc[i][j] = 0.f;

    const int wo  = t >> 2;
    const int wc4 = (t & 3) * 4;
    const int oo  = o0 + wo;
    const float* wrow;
    if (oo < 64)        wrow = wq + (size_t)oo * CC;
    else if (oo < 128)  wrow = wk + (size_t)(oo - 64) * CC;
    else                wrow = wv + (size_t)(oo - 128) * CC;

    const int xc  = t >> 4;
    const int xn4 = (t & 15) * 4;

    for (int c0 = 0; c0 < CC; c0 += 16) {
        float4 w4 = *(const float4*)(wrow + c0 + wc4);
        float4 x4 = *(const float4*)(xb + (size_t)(c0 + xc) * NSEQ + n0 + xn4);
        __syncthreads();
        ws[wc4 + 0][wo] = w4.x; ws[wc4 + 1][wo] = w4.y;
        ws[wc4 + 2][wo] = w4.z; ws[wc4 + 3][wo] = w4.w;
        *(float4*)&xs[xc][xn4] = x4;
        __syncthreads();
#pragma unroll
        for (int c = 0; c < 16; c++) {
            float4 a4 = *(const float4*)&ws[c][4 * ty];
            float4 b4 = *(const float4*)&xs[c][4 * tx];
            float a[4] = {a4.x, a4.y, a4.z, a4.w};
            float bv2[4] = {b4.x, b4.y, b4.z, b4.w};
#pragma unroll
            for (int i = 0; i < 4; i++)
#pragma unroll
                for (int j = 0; j < 4; j++)
                    acc[i][j] = fmaf(a[i], bv2[j], acc[i][j]);
        }
    }

    const int n = n0 + 4 * tx;
#pragma unroll
    for (int mi = 0; mi < 4; mi++) {
        int o = o0 + 4 * ty + mi;
        if (o < 128) {
            int d = o & 63;
            float bias = (o < 64) ? bq[d] : bk[d];
            __half* dh = ((o < 64) ? g_qh : g_kh) + ((size_t)b * NSEQ + n) * DQK + d;
            __half* dl = ((o < 64) ? g_ql : g_kl) + ((size_t)b * NSEQ + n) * DQK + d;
            float vs[4] = {acc[mi][0] + bias, acc[mi][1] + bias,
                           acc[mi][2] + bias, acc[mi][3] + bias};
#pragma unroll
            for (int j = 0; j < 4; j++) {
                __half h = __float2half_rn(vs[j]);
                __half l = __float2half_rn(vs[j] - __half2float(h));
                dh[(size_t)j * DQK] = h;
                dl[(size_t)j * DQK] = l;
            }
        } else {
            int c = o - 128;
            float bias = bv[c];
            size_t off = ((size_t)(b * CC + c)) * NSEQ + n;
            uint2 w2;
            w2.x = pack_h2(acc[mi][0] + bias, acc[mi][1] + bias);
            w2.y = pack_h2(acc[mi][2] + bias, acc[mi][3] + bias);
            *(uint2*)((char*)g_v + off * 2) = w2;
        }
    }
}

// ---------------- pass 2: HMMA fp16 flash attention (online rescale) ---------
// block 128 i x 256 c, 8 warps (warp = 16 i rows, all 256 c), j in 64-chunks,
// double-buffered cp.async K/V tiles, Q resident in SMEM (ldmatrix per chunk).
#define KROW   144
#define S_QHI  0
#define S_QLO  18432
#define S_BUF  36864
#define SK_H   0
#define SK_L   9216
#define SV     18432
#define TILE_BYTES 55296
#define N_CHUNK (NSEQ / 64)
#define CTILE  256
#define STG_ROW 132
#define OUT_SMEM_BYTES (S_BUF + 2 * TILE_BYTES)

__device__ __forceinline__ void issue_tiles(uint32_t tb, int b, int j0, int c0, int t)
{
#pragma unroll
    for (int r = 0; r < 4; r++) {           // K hi+lo: 1024 16B chunks
        int idx = t + r * 256;
        int arr = idx >> 9;
        int row = (idx >> 3) & 63;
        int col = idx & 7;
        const __half* src = (arr ? g_kl : g_kh) + ((size_t)b * NSEQ + j0 + row) * DQK + col * 8;
        cp16(tb + SK_H + arr * 9216 + row * KROW + col * 16, src);
    }
#pragma unroll
    for (int r = 0; r < 8; r++) {           // V: 2048 16B chunks (256 c rows)
        int idx = t + r * 256;
        int row = (idx >> 3) & 255;
        int col = idx & 7;
        const __half* src = g_v + ((size_t)(b * CC + c0 + row)) * NSEQ + j0 + col * 8;
        cp16(tb + SV + row * KROW + col * 16, src);
    }
}

__global__ __launch_bounds__(256, 1) void out_kernel(float* __restrict__ out)
{
    extern __shared__ char smem[];
    const uint32_t sb = smem_u32(smem);
    const int b  = blockIdx.z;
    const int i0 = blockIdx.x * 128;
    const int c0 = blockIdx.y * CTILE;
    const int t  = threadIdx.x;
    const int w  = t >> 5;
    const int lane = t & 31;
    const int g  = lane >> 2;
    const int t4 = lane & 3;
    const int l8 = lane & 7;
    const int tt = lane >> 3;

    // ldmatrix address for Q A-fragments: row (l&7)+((l>>3)&1)*8, col-half (l>>4)*8
    const uint32_t qlrow = (uint32_t)(w * 16 + l8 + ((lane >> 3) & 1) * 8) * KROW
                         + (uint32_t)((lane >> 4) * 16);

    // stage Q hi/lo [128 i][64 d] into SMEM via cp.async
#pragma unroll
    for (int r = 0; r < 8; r++) {
        int idx = t + r * 256;
        int arr = idx >> 10;
        int row = (idx >> 3) & 127;
        int col = idx & 7;
        const __half* src = (arr ? g_ql : g_qh) + ((size_t)b * NSEQ + i0 + row) * DQK + col * 8;
        cp16(sb + S_QHI + arr * 18432 + row * KROW + col * 16, src);
    }
    issue_tiles(sb + S_BUF, b, 0, c0, t);
    CP_COMMIT();

    float o[CTILE / 8][4];
#pragma unroll
    for (int ct = 0; ct < CTILE / 8; ct++)
#pragma unroll
        for (int r = 0; r < 4; r++) o[ct][r] = 0.f;
    float m0 = -1e30f, m1 = -1e30f;     // running row max (log2 units)
    float lsum0 = 0.f, lsum1 = 0.f;     // row sums in current frame

    for (int it = 0; it < N_CHUNK; ++it) {
        if (it + 1 < N_CHUNK)
            issue_tiles(sb + S_BUF + ((it + 1) & 1) * TILE_BYTES, b, (it + 1) * 64, c0, t);
        CP_COMMIT();
        CP_WAIT1();
        __syncthreads();

        const uint32_t tb = sb + S_BUF + (it & 1) * TILE_BYTES;

        // ---- GEMM1: S = Q K^T (fp16 split-3), Q from SMEM ----
        float s[8][4];
#pragma unroll
        for (int nt = 0; nt < 8; nt++)
#pragma unroll
            for (int r = 0; r < 4; r++) s[nt][r] = 0.f;

#pragma unroll
        for (int grp = 0; grp < 2; grp++) {
#pragma unroll
            for (int kp = 0; kp < 2; kp++) {
                uint32_t qh0[4], qh1[4], ql0[4], ql1[4];
                uint32_t qcol = (uint32_t)(kp * 64);
                ldsm4(qh0, sb + S_QHI + qlrow + qcol);
                ldsm4(qh1, sb + S_QHI + qlrow + qcol + 32);
                ldsm4(ql0, sb + S_QLO + qlrow + qcol);
                ldsm4(ql1, sb + S_QLO + qlrow + qcol + 32);
#pragma unroll
                for (int q = 0; q < 4; q++) {
                    int nt = grp * 4 + q;
                    uint32_t krow = tb + (nt * 8 + l8) * KROW + tt * 16;
                    uint32_t kh[4], kl[4];
                    ldsm4(kh, krow + SK_H + kp * 64);
                    ldsm4(kl, krow + SK_L + kp * 64);
                    mma_f16(s[nt], qh0, kh[0], kh[1]);
                    mma_f16(s[nt], qh1, kh[2], kh[3]);
                    mma_f16(s[nt], ql0, kh[0], kh[1]);
                    mma_f16(s[nt], ql1, kh[2], kh[3]);
                    mma_f16(s[nt], qh0, kl[0], kl[1]);
                    mma_f16(s[nt], qh1, kl[2], kl[3]);
                }
            }
        }

        // ---- online rescale: chunk max -> update frame ----
        float cm0 = -1e30f, cm1 = -1e30f;
#pragma unroll
        for (int nt = 0; nt < 8; nt++) {
            cm0 = fmaxf(cm0, fmaxf(s[nt][0], s[nt][1]));
            cm1 = fmaxf(cm1, fmaxf(s[nt][2], s[nt][3]));
        }
        cm0 = fmaxf(cm0, __shfl_xor_sync(0xFFFFFFFFu, cm0, 1));
        cm0 = fmaxf(cm0, __shfl_xor_sync(0xFFFFFFFFu, cm0, 2));
        cm1 = fmaxf(cm1, __shfl_xor_sync(0xFFFFFFFFu, cm1, 1));
        cm1 = fmaxf(cm1, __shfl_xor_sync(0xFFFFFFFFu, cm1, 2));
        float m0n = fmaxf(m0, cm0 * LOG2E);
        float m1n = fmaxf(m1, cm1 * LOG2E);
        float f0 = exp2_fast(m0 - m0n);
        float f1 = exp2_fast(m1 - m1n);
        m0 = m0n; m1 = m1n;
        lsum0 *= f0; lsum1 *= f1;
        if (__any_sync(0xFFFFFFFFu, fminf(f0, f1) < 0.9999995f)) {
#pragma unroll
            for (int ct = 0; ct < CTILE / 8; ct++) {
                o[ct][0] *= f0; o[ct][1] *= f0;
                o[ct][2] *= f1; o[ct][3] *= f1;
            }
        }

        // ---- softmax exp + pack P (fp16, <=1) ----
        uint32_t pa[4][4];
#pragma unroll
        for (int kt4 = 0; kt4 < 4; kt4++)
#pragma unroll
            for (int h = 0; h < 2; h++) {
                int nt = kt4 * 2 + h;
                float p0 = exp2_fast(fmaf(s[nt][0], LOG2E, -m0));
                float p1 = exp2_fast(fmaf(s[nt][1], LOG2E, -m0));
                float p2 = exp2_fast(fmaf(s[nt][2], LOG2E, -m1));
                float p3 = exp2_fast(fmaf(s[nt][3], LOG2E, -m1));
                lsum0 += p0 + p1;
                lsum1 += p2 + p3;
                pa[kt4][2 * h + 0] = pack_h2(p0, p1);
                pa[kt4][2 * h + 1] = pack_h2(p2, p3);
            }

        // ---- GEMM2: O += P V^T (fp16 single) ----
#pragma unroll
        for (int ct = 0; ct < CTILE / 8; ct++) {
            uint32_t vrow = tb + SV + (ct * 8 + l8) * KROW + tt * 16;
#pragma unroll
            for (int jh = 0; jh < 2; jh++) {
                uint32_t vv[4];
                ldsm4(vv, vrow + jh * 64);
                mma_f16(o[ct], pa[2 * jh],     vv[0], vv[1]);
                mma_f16(o[ct], pa[2 * jh + 1], vv[2], vv[3]);
            }
        }
        __syncthreads();
    }

    // reduce row sums across the 4 lanes sharing a row
    lsum0 += __shfl_xor_sync(0xFFFFFFFFu, lsum0, 1);
    lsum0 += __shfl_xor_sync(0xFFFFFFFFu, lsum0, 2);
    lsum1 += __shfl_xor_sync(0xFFFFFFFFu, lsum1, 1);
    lsum1 += __shfl_xor_sync(0xFFFFFFFFu, lsum1, 2);
    const float li0 = 1.0f / lsum0;
    const float li1 = 1.0f / lsum1;

    // epilogue: scale by 1/l, transpose through SMEM staging, coalesced store
    float* stg = (float*)smem;
    const int il = w * 16 + g;
#pragma unroll
    for (int ct = 0; ct < CTILE / 8; ct++) {
        int c = ct * 8 + 2 * t4;
        stg[(size_t)c * STG_ROW + il]           = o[ct][0] * li0;
        stg[(size_t)(c + 1) * STG_ROW + il]     = o[ct][1] * li0;
        stg[(size_t)c * STG_ROW + il + 8]       = o[ct][2] * li1;
        stg[(size_t)(c + 1) * STG_ROW + il + 8] = o[ct][3] * li1;
    }
    __syncthreads();
#pragma unroll
    for (int r = 0; r < CTILE / 8; r++) {
        int fid = t + r * 256;
        int c = fid >> 5, x = fid & 31;
        float4 v = *(const float4*)&stg[(size_t)c * STG_ROW + x * 4];
        *(float4*)(out + ((size_t)(b * CC + c0 + c)) * NSEQ + i0 + x * 4) = v;
    }
}

// ---------------- launch ----------------------------------------------------
extern "C" void kernel_launch(void* const* d_in, const int* in_sizes, int n_in,
                              void* d_out, int out_size)
{
    const float* x  = (const float*)d_in[0];
    const float* wq = (const float*)d_in[1];
    const float* bq = (const float*)d_in[2];
    const float* wk = (const float*)d_in[3];
    const float* bk = (const float*)d_in[4];
    const float* wv = (const float*)d_in[5];
    const float* bv = (const float*)d_in[6];
    float* out = (float*)d_out;

    proj_kernel<<<dim3(NSEQ / 64, 640 / 64, BB), 256>>>(x, wq, bq, wk, bk, wv, bv);
    cudaFuncSetAttribute(out_kernel, cudaFuncAttributeMaxDynamicSharedMemorySize, OUT_SMEM_BYTES);
    out_kernel<<<dim3(NSEQ / 128, CC / CTILE, BB), 256, OUT_SMEM_BYTES>>>(out);
}